// round 17
// baseline (speedup 1.0000x reference)
#include <cuda_runtime.h>
#include <cuda_fp16.h>
#include <math.h>
#include <stdint.h>

#define BB 2
#define CC 128
#define NN 8192
#define PTS 4
#define THREADS 256
#define TWO_PI 6.283185307179586f
#define RSQRT_C 0.08838834764831845f   // 1/sqrt(128)

// ---------------- device scratch ----------------
__device__ __half g_xsTh[BB * NN * CC];    // xs transposed to [B][N][C], fp16
__device__ __half g_Qph[BB * NN * 160];    // per point: [0..127]=Q', [128..159]=Q'' (fp16)
__device__ __half g_vh [BB * NN * 160];    // attention aggregates [n][160], fp16
__device__ float  g_p0[CC];                // Wk^T bq
__device__ float  g_pq0[32];               // W2 p0
__device__ float  g_Wcat[160 * CC];        // fp32 staging of Wfuse (rows 0..127 used)
__device__ float  g_b3[CC];                // fused output bias
__device__ __half g_W1h[32 * 128];         // W1^T [j][d], fp16
__device__ __half g_Bh[160 * 128];         // pre GEMM B: rows 0..127 P[c][i], 128..159 Pq[j][i]
__device__ __half g_Wcath[128 * 160];      // out GEMM B: Wfused[o][i], i in 0..159
__device__ int    g_idx64;

// ---------------- mma helpers ----------------
__device__ __forceinline__ void ldmatrix_x4(uint32_t* a, uint32_t saddr) {
    asm volatile("ldmatrix.sync.aligned.m8n8.x4.shared.b16 {%0,%1,%2,%3}, [%4];"
                 : "=r"(a[0]), "=r"(a[1]), "=r"(a[2]), "=r"(a[3]) : "r"(saddr));
}
__device__ __forceinline__ void ldmatrix_x2(uint32_t& b0, uint32_t& b1, uint32_t saddr) {
    asm volatile("ldmatrix.sync.aligned.m8n8.x2.shared.b16 {%0,%1}, [%2];"
                 : "=r"(b0), "=r"(b1) : "r"(saddr));
}
__device__ __forceinline__ void mma16816(float* c, const uint32_t* a, uint32_t b0, uint32_t b1) {
    asm volatile("mma.sync.aligned.m16n8k16.row.col.f32.f16.f16.f32 "
                 "{%0,%1,%2,%3}, {%4,%5,%6,%7}, {%8,%9}, {%0,%1,%2,%3};"
                 : "+f"(c[0]), "+f"(c[1]), "+f"(c[2]), "+f"(c[3])
                 : "r"(a[0]), "r"(a[1]), "r"(a[2]), "r"(a[3]), "r"(b0), "r"(b1));
}

// ---------------- prep1: all weight fusion except W3/b3 (+ idx detect) ----------------
__global__ void prep1_kernel(const float* __restrict__ Wq, const float* __restrict__ Wk,
                             const float* __restrict__ Wv, const float* __restrict__ Wo,
                             const float* __restrict__ bq, const float* __restrict__ W2,
                             const float* __restrict__ W1, const int* __restrict__ idx32) {
    int i = blockIdx.x, t = threadIdx.x;
    if (i == 128) {
        __shared__ int any;
        if (t == 0) any = 0;
        __syncthreads();
        int local = 0;
        for (int e = t; e < 2048; e += 128)
            if (idx32[2 * e + 1] != 0) local = 1;
        if (local) atomicOr(&any, 1);
        __syncthreads();
        if (t == 0) g_idx64 = (any ? 0 : 1);
        return;
    }
    __shared__ float s[128];
    __shared__ float s2[128];
    float a = 0.f, w = 0.f;
    for (int o = 0; o < 128; ++o) {
        a += Wk[o * 128 + t] * Wq[o * 128 + i];   // P[t][i]
        w += Wo[t * 128 + o] * Wv[o * 128 + i];   // Wfuse[t][i]
    }
    g_Wcat[i * 128 + t] = w;
    g_Wcath[t * 160 + i] = __float2half(w);
    g_Bh[t * 128 + i] = __float2half(a);
    s[t] = a;
    if (i == 0) {
        float p = 0.f;
        for (int o = 0; o < 128; ++o) p += Wk[o * 128 + t] * bq[o];
        g_p0[t] = p;
        s2[t] = p;
    }
    __syncthreads();
    if (t < 32) {
        float acc = 0.f;
        for (int c = 0; c < 128; ++c) acc += W2[t * 128 + c] * s[c];
        g_Bh[(128 + t) * 128 + i] = __float2half(acc);   // Pq[t][i]
        g_W1h[t * 128 + i] = __float2half(W1[i * 32 + t]);
        if (i == 0) {
            float q = 0.f;
            for (int c = 0; c < 128; ++c) q += W2[t * 128 + c] * s2[c];
            g_pq0[t] = q;
        }
    }
}

// ---------------- pre kernel: 64 pts/block GEMM; extra blocks do W3/b3 ----------------
struct __align__(16) SMPRE {
    __half As[64][136];    // x^T tile [pt][c]
    __half Bs[160][136];   // [P;Pq] [chan][i]
};
__global__ __launch_bounds__(256) void pre_kernel(
    const float* __restrict__ x, const float* __restrict__ W2,
    const float* __restrict__ b2, const float* __restrict__ bv,
    const float* __restrict__ bo, const float* __restrict__ Wo) {
    const int blk = blockIdx.x;
    const int t = threadIdx.x;

    if (blk >= 256) {
        int j = blk - 256;                 // 0..31
        if (t < 128) {
            float acc = 0.f;
            for (int ii = 0; ii < 128; ++ii)
                acc += g_Wcat[ii * 128 + t] * W2[j * 128 + ii];
            g_Wcath[t * 160 + 128 + j] = __float2half(acc);
        } else if (j == 0) {
            int tt = t - 128;
            float a = 0.f;
            for (int ii = 0; ii < 128; ++ii) a += g_Wcat[ii * 128 + tt] * b2[ii];
            for (int c = 0; c < 128; ++c)   a += Wo[tt * 128 + c] * bv[c];
            g_b3[tt] = a + bo[tt];
        }
        return;
    }

    extern __shared__ char smem_raw[];
    SMPRE* sm = reinterpret_cast<SMPRE*>(smem_raw);
    const int lane = t & 31, w = t >> 5;
    const int b = blk >> 7;
    const int n0 = (blk & 127) << 6;
    const size_t gbase = (size_t)b * NN + n0;

    #pragma unroll
    for (int m = 0; m < 32; ++m) {
        int e = (m << 8) + t;
        int c = e >> 6, nn = e & 63;
        sm->As[nn][c] = __float2half(x[((size_t)(b * 128 + c) << 13) + n0 + nn]);
    }
    #pragma unroll
    for (int m = 0; m < 10; ++m) {
        int e = (m << 8) + t;
        int row = e >> 4, col8 = (e & 15) << 3;
        *(uint4*)&sm->Bs[row][col8] = *(const uint4*)&g_Bh[row * 128 + col8];
    }
    __syncthreads();

    #pragma unroll
    for (int m = 0; m < 4; ++m) {
        int e = (m << 8) + t;
        int row = e >> 4, col8 = (e & 15) << 3;
        *(uint4*)&g_xsTh[(gbase + row) * 128 + col8] = *(const uint4*)&sm->As[row][col8];
    }

    const int mt = w & 3, ng = w >> 2;
    const int r0 = mt << 4;
    float c[10][4];
    #pragma unroll
    for (int nt = 0; nt < 10; ++nt)
        #pragma unroll
        for (int q = 0; q < 4; ++q) c[nt][q] = 0.f;

    #pragma unroll
    for (int ks = 0; ks < 8; ++ks) {
        int k0 = ks << 4;
        uint32_t A[4];
        const __half* ea = &sm->As[r0 + (lane & 15)][k0 + ((lane >> 4) << 3)];
        ldmatrix_x4(A, (uint32_t)__cvta_generic_to_shared(ea));
        #pragma unroll
        for (int nt = 0; nt < 10; ++nt) {
            uint32_t b0, b1v;
            const __half* wb = &sm->Bs[ng * 80 + (nt << 3) + (lane & 7)]
                                      [k0 + (((lane >> 3) & 1) << 3)];
            ldmatrix_x2(b0, b1v, (uint32_t)__cvta_generic_to_shared(wb));
            mma16816(c[nt], A, b0, b1v);
        }
    }

    {
        const int pt = r0 + (lane >> 2);
        #pragma unroll
        for (int nt = 0; nt < 10; ++nt) {
            int chan = ng * 80 + (nt << 3) + ((lane & 3) << 1);
            float bx, by;
            if (chan < 128) {
                bx = __ldg(&g_p0[chan]); by = __ldg(&g_p0[chan + 1]);
            } else {
                bx = __ldg(&g_pq0[chan - 128]); by = __ldg(&g_pq0[chan - 127]);
            }
            __half2 h0 = __floats2half2_rn(c[nt][0] + bx, c[nt][1] + by);
            __half2 h1 = __floats2half2_rn(c[nt][2] + bx, c[nt][3] + by);
            *(__half2*)&g_Qph[(gbase + pt) * 160 + chan]     = h0;
            *(__half2*)&g_Qph[(gbase + pt + 8) * 160 + chan] = h1;
        }
    }
}

// ---------------- shared memory layout for main (~52KB) ----------------
struct __align__(16) SM {
    __half E[64][136];
    __half W1s[32][136];
    float rh[64][34];
    float lp[64][36];      // per-lane logit partials (rows 16B-aligned)
    __half Qph_s[4][160];  // fp16 Q'/Q'' per point
    float dp[64][4];
    float Bg[256];         // linear: 2pi * Bg[a*64+d]
    float vpart[8][128];
    float attn[64];
    float rden[4];
    float ctr[4][4];
    int   idx[64];
};

// ---------------- main kernel: 4 points/block ----------------
__global__ __launch_bounds__(THREADS, 4) void lsga_main_kernel(
    const float* __restrict__ coords, const void* __restrict__ idxp,
    const float* __restrict__ Bg, const float* __restrict__ b1) {

    extern __shared__ char smem_raw[];
    SM* sm = reinterpret_cast<SM*>(smem_raw);

    const int t = threadIdx.x;
    const int lane = t & 31;
    const int w = t >> 5;
    const int g0 = blockIdx.x * PTS;
    const int b = g0 >> 13;
    const int n0 = g0 & (NN - 1);
    const size_t base = (size_t)b * NN + n0;

    // ---- P0: loads ----
    if (t < 80) {
        int p = t / 20, q = t % 20;
        *(uint4*)&sm->Qph_s[p][q << 3] = *(const uint4*)&g_Qph[(base + p) * 160 + (q << 3)];
    }
    sm->Bg[t] = Bg[t] * TWO_PI;
    #pragma unroll
    for (int m = 0; m < 2; ++m) {
        int e = (m << 8) + t;
        int j = e >> 4, c0 = (e & 15) << 3;
        *(uint4*)&sm->W1s[j][c0] = *(const uint4*)&g_W1h[j * 128 + c0];
    }
    if (t < 64) {
        long long v;
        if (g_idx64) v = ((const long long*)idxp)[base * 16 + t];
        else         v = (long long)((const int*)idxp)[base * 16 + t];
        sm->idx[t] = (int)v;
    }
    if (t < 16) {
        int p = t >> 2, a = t & 3;
        sm->ctr[p][a] = coords[(base + p) * 4 + a];
    }
    __syncthreads();

    // ---- P1: delta-p + fp16 neighbor gather into registers ----
    {
        int r = t >> 2, a = t & 3, p = t >> 6;
        sm->dp[r][a] = coords[((size_t)b * NN + sm->idx[r]) * 4 + a] - sm->ctr[p][a];
    }
    float4 nbf[8];
    #pragma unroll
    for (int rr = 0; rr < 8; ++rr) {
        int r = (w << 3) + rr;
        uint2 hv = __ldg((const uint2*)(g_xsTh + ((size_t)b * NN + sm->idx[r]) * 128) + lane);
        __half2* hp = (__half2*)&hv;
        float2 f0 = __half22float2(hp[0]);
        float2 f1 = __half22float2(hp[1]);
        nbf[rr] = make_float4(f0.x, f0.y, f1.x, f1.y);
    }
    __syncthreads();

    // ---- P2: Fourier sincos -> fp16 E (4 consecutive d per thread, STS.64) ----
    {
        const int rb = t >> 4;
        const int dq = (t & 15) << 2;
        #pragma unroll
        for (int m = 0; m < 4; ++m) {
            int r = (m << 4) + rb;
            float4 dpv = *(const float4*)sm->dp[r];
            float sv[4], cv[4];
            #pragma unroll
            for (int q = 0; q < 4; ++q) {
                int d = dq + q;
                float pr = dpv.x * sm->Bg[d]
                         + dpv.y * sm->Bg[64 + d]
                         + dpv.z * sm->Bg[128 + d]
                         + dpv.w * sm->Bg[192 + d];
                __sincosf(pr, &sv[q], &cv[q]);
            }
            __half2 s01 = __floats2half2_rn(sv[0], sv[1]);
            __half2 s23 = __floats2half2_rn(sv[2], sv[3]);
            __half2 c01 = __floats2half2_rn(cv[0], cv[1]);
            __half2 c23 = __floats2half2_rn(cv[2], cv[3]);
            *(uint2*)&sm->E[r][dq]      = make_uint2(*(uint32_t*)&s01, *(uint32_t*)&s23);
            *(uint2*)&sm->E[r][64 + dq] = make_uint2(*(uint32_t*)&c01, *(uint32_t*)&c23);
        }
    }
    __syncthreads();

    // ---- P3: hidden MLP via tensor cores, m16 x n16 x k128 per warp ----
    {
        const int mtile = w & 3;
        const int nh = w >> 2;
        const int r0 = mtile << 4;
        const int jn0 = nh << 4;

        float c[2][4];
        #pragma unroll
        for (int nt = 0; nt < 2; ++nt)
            #pragma unroll
            for (int q = 0; q < 4; ++q) c[nt][q] = 0.f;

        #pragma unroll
        for (int ks = 0; ks < 8; ++ks) {
            int k0 = ks << 4;
            uint32_t A[4];
            const __half* ea = &sm->E[r0 + (lane & 15)][k0 + ((lane >> 4) << 3)];
            ldmatrix_x4(A, (uint32_t)__cvta_generic_to_shared(ea));
            #pragma unroll
            for (int nt = 0; nt < 2; ++nt) {
                uint32_t b0, b1v;
                const __half* wb = &sm->W1s[jn0 + (nt << 3) + (lane & 7)]
                                          [k0 + (((lane >> 3) & 1) << 3)];
                ldmatrix_x2(b0, b1v, (uint32_t)__cvta_generic_to_shared(wb));
                mma16816(c[nt], A, b0, b1v);
            }
        }

        const int row1 = r0 + (lane >> 2);
        #pragma unroll
        for (int nt = 0; nt < 2; ++nt) {
            int col = jn0 + (nt << 3) + ((lane & 3) << 1);
            float bb0 = __ldg(&b1[col]), bb1 = __ldg(&b1[col + 1]);
            *(float2*)&sm->rh[row1][col] =
                make_float2(fmaxf(c[nt][0] + bb0, 0.f), fmaxf(c[nt][1] + bb1, 0.f));
            *(float2*)&sm->rh[row1 + 8][col] =
                make_float2(fmaxf(c[nt][2] + bb0, 0.f), fmaxf(c[nt][3] + bb1, 0.f));
        }
    }
    __syncthreads();

    // ---- P5: logit partials to smem (no shuffles) ----
    {
        const int p = w >> 1;
        uint2 qh = *(const uint2*)&sm->Qph_s[p][lane << 2];
        __half2* qhp = (__half2*)&qh;
        float2 q01 = __half22float2(qhp[0]);
        float2 q23 = __half22float2(qhp[1]);
        float qpp = __half2float(sm->Qph_s[p][128 + lane]);
        #pragma unroll
        for (int rr = 0; rr < 8; ++rr) {
            int r = (w << 3) + rr;
            sm->lp[r][lane] = q01.x * nbf[rr].x + q01.y * nbf[rr].y
                            + q23.x * nbf[rr].z + q23.y * nbf[rr].w
                            + sm->rh[r][lane] * qpp;
        }
    }
    __syncthreads();

    // ---- P6: reduce (float4) + softmax ----
    if (t < 64) {
        const float4* lpr = (const float4*)sm->lp[t];
        float4 a0 = lpr[0], a1 = lpr[1], a2 = lpr[2], a3 = lpr[3];
        float4 a4 = lpr[4], a5 = lpr[5], a6 = lpr[6], a7 = lpr[7];
        float s = ((a0.x + a0.y) + (a0.z + a0.w)) + ((a1.x + a1.y) + (a1.z + a1.w))
                + ((a2.x + a2.y) + (a2.z + a2.w)) + ((a3.x + a3.y) + (a3.z + a3.w))
                + ((a4.x + a4.y) + (a4.z + a4.w)) + ((a5.x + a5.y) + (a5.z + a5.w))
                + ((a6.x + a6.y) + (a6.z + a6.w)) + ((a7.x + a7.y) + (a7.z + a7.w));
        float lg = s * RSQRT_C;
        int p = t >> 4, k = t & 15;
        float mx = lg;
        #pragma unroll
        for (int off = 8; off; off >>= 1)
            mx = fmaxf(mx, __shfl_xor_sync(0xffffffffu, mx, off));
        float e = __expf(lg - mx);
        float ssum = e;
        #pragma unroll
        for (int off = 8; off; off >>= 1)
            ssum += __shfl_xor_sync(0xffffffffu, ssum, off);
        sm->attn[t] = e;
        if (k == 0) sm->rden[p] = 1.0f / ssum;
    }
    __syncthreads();

    // ---- P7: aggregates -> g_vh (fp16) ----
    {
        float4 fa = make_float4(0.f, 0.f, 0.f, 0.f);
        #pragma unroll
        for (int rr = 0; rr < 8; ++rr) {
            float a = sm->attn[(w << 3) + rr];
            fa.x = fmaf(a, nbf[rr].x, fa.x);
            fa.y = fmaf(a, nbf[rr].y, fa.y);
            fa.z = fmaf(a, nbf[rr].z, fa.z);
            fa.w = fmaf(a, nbf[rr].w, fa.w);
        }
        *(float4*)&sm->vpart[w][lane << 2] = fa;
    }
    if (t < 128) {
        int p = t >> 5, j = t & 31;
        float ha = 0.f;
        #pragma unroll
        for (int k = 0; k < 16; ++k)
            ha = fmaf(sm->attn[p * 16 + k], sm->rh[p * 16 + k][j], ha);
        g_vh[(base + p) * 160 + 128 + j] = __float2half(ha * sm->rden[p]);
    }
    __syncthreads();

    // combine vpart halves, half2 stores (one per thread)
    {
        int p = t >> 6, c2 = (t & 63) << 1;
        float rd = sm->rden[p];
        float2 va = *(const float2*)&sm->vpart[2 * p][c2];
        float2 vb = *(const float2*)&sm->vpart[2 * p + 1][c2];
        *(__half2*)&g_vh[(base + p) * 160 + c2] =
            __floats2half2_rn((va.x + vb.x) * rd, (va.y + vb.y) * rd);
    }
}

// ---------------- out kernel: 64 points/block, direct STG epilogue ----------------
struct __align__(16) SMOUT {
    __half As[64][168];    // v [pt][i]
    __half Bs[128][168];   // Wfused [o][i]
};
__global__ __launch_bounds__(256) void out_kernel(float* __restrict__ out) {
    extern __shared__ char smem_raw[];
    SMOUT* sm = reinterpret_cast<SMOUT*>(smem_raw);
    const int t = threadIdx.x;
    const int lane = t & 31, w = t >> 5;
    const int blk = blockIdx.x;               // 0..255
    const int b = blk >> 7;
    const int n0 = (blk & 127) << 6;
    const size_t gbase = (size_t)b * NN + n0;

    #pragma unroll
    for (int m = 0; m < 5; ++m) {
        int e = (m << 8) + t;
        int row = e / 20, col8 = (e % 20) << 3;
        *(uint4*)&sm->As[row][col8] = *(const uint4*)&g_vh[(gbase + row) * 160 + col8];
    }
    #pragma unroll
    for (int m = 0; m < 10; ++m) {
        int e = (m << 8) + t;
        int row = e / 20, col8 = (e % 20) << 3;
        *(uint4*)&sm->Bs[row][col8] = *(const uint4*)&g_Wcath[row * 160 + col8];
    }
    __syncthreads();

    const int mt = w & 3, ng = w >> 2;
    const int r0 = mt << 4;
    float c[8][4];
    #pragma unroll
    for (int nt = 0; nt < 8; ++nt)
        #pragma unroll
        for (int q = 0; q < 4; ++q) c[nt][q] = 0.f;

    #pragma unroll
    for (int ks = 0; ks < 10; ++ks) {
        int k0 = ks << 4;
        uint32_t A[4];
        const __half* ea = &sm->As[r0 + (lane & 15)][k0 + ((lane >> 4) << 3)];
        ldmatrix_x4(A, (uint32_t)__cvta_generic_to_shared(ea));
        #pragma unroll
        for (int nt = 0; nt < 8; ++nt) {
            uint32_t b0, b1v;
            const __half* wb = &sm->Bs[(ng << 6) + (nt << 3) + (lane & 7)]
                                      [k0 + (((lane >> 3) & 1) << 3)];
            ldmatrix_x2(b0, b1v, (uint32_t)__cvta_generic_to_shared(wb));
            mma16816(c[nt], A, b0, b1v);
        }
    }

    // direct STG epilogue
    {
        const int pt = r0 + (lane >> 2);
        #pragma unroll
        for (int nt = 0; nt < 8; ++nt) {
            int chan = (ng << 6) + (nt << 3) + ((lane & 3) << 1);
            float bx = __ldg(&g_b3[chan]), by = __ldg(&g_b3[chan + 1]);
            float* row0 = &out[((size_t)(b * 128 + chan) << 13) + n0];
            float* row1 = row0 + NN;
            row0[pt]     = c[nt][0] + bx;
            row1[pt]     = c[nt][1] + by;
            row0[pt + 8] = c[nt][2] + bx;
            row1[pt + 8] = c[nt][3] + by;
        }
    }
}

// ---------------- launch ----------------
extern "C" void kernel_launch(void* const* d_in, const int* in_sizes, int n_in,
                              void* d_out, int out_size) {
    const float* x      = (const float*)d_in[0];
    const float* coords = (const float*)d_in[1];
    const void*  idx    = d_in[2];
    const float* Bg     = (const float*)d_in[3];
    const float* W1     = (const float*)d_in[4];
    const float* b1     = (const float*)d_in[5];
    const float* W2     = (const float*)d_in[6];
    const float* b2     = (const float*)d_in[7];
    const float* Wq     = (const float*)d_in[8];
    const float* bq     = (const float*)d_in[9];
    const float* Wk     = (const float*)d_in[10];
    const float* Wv     = (const float*)d_in[12];
    const float* bv     = (const float*)d_in[13];
    const float* Wo     = (const float*)d_in[14];
    const float* bo     = (const float*)d_in[15];
    float* out = (float*)d_out;

    static bool attr_set = false;
    if (!attr_set) {
        cudaFuncSetAttribute(lsga_main_kernel,
                             cudaFuncAttributeMaxDynamicSharedMemorySize, (int)sizeof(SM));
        cudaFuncSetAttribute(pre_kernel,
                             cudaFuncAttributeMaxDynamicSharedMemorySize, (int)sizeof(SMPRE));
        cudaFuncSetAttribute(out_kernel,
                             cudaFuncAttributeMaxDynamicSharedMemorySize, (int)sizeof(SMOUT));
        attr_set = true;
    }

    prep1_kernel<<<129, 128>>>(Wq, Wk, Wv, Wo, bq, W2, W1, (const int*)idx);
    pre_kernel<<<288, 256, sizeof(SMPRE)>>>(x, W2, b2, bv, bo, Wo);
    lsga_main_kernel<<<(BB * NN) / PTS, THREADS, sizeof(SM)>>>(coords, idx, Bg, b1);
    out_kernel<<<(BB * NN) / 64, 256, sizeof(SMOUT)>>>(out);
}